// round 2
// baseline (speedup 1.0000x reference)
#include <cuda_runtime.h>
#include <math.h>

// RegionalAttentionPool: B=16, N=4096, D=512, R=64, K=128
// out[b,r,d] = sum_k softmax_k( x[b, idx[r,k], :] . W + bias ) * x[b, idx[r,k], d]
//
// Strategy: one CTA per (b,r). 512 threads, thread = one d element.
// Online softmax so each gathered row is read from memory exactly once.

constexpr int Bc = 16;
constexpr int Nc = 4096;
constexpr int Dc = 512;
constexpr int Rc = 64;
constexpr int Kc = 128;
constexpr int GROUP = 8;   // k's processed per barrier pair (also load MLP depth)

__global__ __launch_bounds__(512, 2)
void regional_attn_pool(const float* __restrict__ x,
                        const int*   __restrict__ ridx,
                        const float* __restrict__ W,
                        const float* __restrict__ bias,
                        float*       __restrict__ out)
{
    __shared__ int   s_idx[Kc];
    __shared__ float s_part[GROUP][16];
    __shared__ float s_score[GROUP];

    const int d    = threadIdx.x;          // 0..511
    const int lane = d & 31;
    const int warp = d >> 5;               // 0..15
    const int r    = blockIdx.x % Rc;
    const int b    = blockIdx.x / Rc;

    if (d < Kc) s_idx[d] = ridx[r * Kc + d];
    const float w_d = W[d];
    const float b0  = bias[0];
    __syncthreads();

    const float* __restrict__ xb = x + (size_t)b * (Nc * Dc);

    float m   = -3.402823466e38f;   // running max
    float l   = 0.0f;               // running denom
    float acc = 0.0f;               // running weighted sum for this d

    // prefetch group 0
    float v[GROUP];
    #pragma unroll
    for (int j = 0; j < GROUP; j++)
        v[j] = xb[(size_t)s_idx[j] * Dc + d];

    #pragma unroll 1
    for (int g = 0; g < Kc / GROUP; g++) {
        // issue next group's loads early (hidden behind reduce + barriers)
        float nv[GROUP];
        const bool more = (g + 1 < Kc / GROUP);
        if (more) {
            #pragma unroll
            for (int j = 0; j < GROUP; j++)
                nv[j] = xb[(size_t)s_idx[(g + 1) * GROUP + j] * Dc + d];
        }

        // partial dot products for the current group
        float p[GROUP];
        #pragma unroll
        for (int j = 0; j < GROUP; j++) p[j] = w_d * v[j];

        // stage 1: intra-warp tree reduce (all 8 k's interleaved for ILP)
        #pragma unroll
        for (int off = 16; off > 0; off >>= 1) {
            #pragma unroll
            for (int j = 0; j < GROUP; j++)
                p[j] += __shfl_xor_sync(0xffffffffu, p[j], off);
        }
        if (lane == 0) {
            #pragma unroll
            for (int j = 0; j < GROUP; j++) s_part[j][warp] = p[j];
        }
        __syncthreads();

        // stage 2: warps 0..7 each reduce the 16 warp-partials of one k
        if (warp < GROUP) {
            float t = (lane < 16) ? s_part[warp][lane] : 0.0f;
            #pragma unroll
            for (int off = 8; off > 0; off >>= 1)
                t += __shfl_xor_sync(0xffffffffu, t, off);
            if (lane == 0) s_score[warp] = t + b0;
        }
        __syncthreads();

        // online softmax update, all in registers
        #pragma unroll
        for (int j = 0; j < GROUP; j++) {
            float s  = s_score[j];
            float mn = fmaxf(m, s);
            float c  = __expf(m - mn);
            float e  = __expf(s - mn);
            l   = fmaf(l,   c, e);
            acc = fmaf(acc, c, e * v[j]);
            m   = mn;
        }

        if (more) {
            #pragma unroll
            for (int j = 0; j < GROUP; j++) v[j] = nv[j];
        }
    }

    out[(size_t)blockIdx.x * Dc + d] = acc / l;
}

extern "C" void kernel_launch(void* const* d_in, const int* in_sizes, int n_in,
                              void* d_out, int out_size)
{
    const float* x    = (const float*)d_in[0];   // (B, N, D) f32
    const int*   ridx = (const int*)  d_in[1];   // (R, K) i32
    const float* W    = (const float*)d_in[2];   // (1, D) f32
    const float* bias = (const float*)d_in[3];   // (1,) f32
    float*       out  = (float*)d_out;           // (B, R, D) f32

    regional_attn_pool<<<Bc * Rc, Dc>>>(x, ridx, W, bias, out);
}

// round 3
// speedup vs baseline: 1.0018x; 1.0018x over previous
#include <cuda_runtime.h>
#include <math.h>

// RegionalAttentionPool: B=16, N=4096, D=512, R=64, K=128
// out[b,r,d] = sum_k softmax_k( x[b, idx[r,k], :] . W + bias ) * x[b, idx[r,k], d]
//
// Strategy: one CTA per (b,r). 512 threads, thread = one d element.
// Online softmax so each gathered row is read from memory exactly once.

constexpr int Bc = 16;
constexpr int Nc = 4096;
constexpr int Dc = 512;
constexpr int Rc = 64;
constexpr int Kc = 128;
constexpr int GROUP = 8;   // k's processed per barrier pair (also load MLP depth)

__global__ __launch_bounds__(512, 2)
void regional_attn_pool(const float* __restrict__ x,
                        const int*   __restrict__ ridx,
                        const float* __restrict__ W,
                        const float* __restrict__ bias,
                        float*       __restrict__ out)
{
    __shared__ int   s_idx[Kc];
    __shared__ float s_part[GROUP][16];
    __shared__ float s_score[GROUP];

    const int d    = threadIdx.x;          // 0..511
    const int lane = d & 31;
    const int warp = d >> 5;               // 0..15
    const int r    = blockIdx.x % Rc;
    const int b    = blockIdx.x / Rc;

    if (d < Kc) s_idx[d] = ridx[r * Kc + d];
    const float w_d = W[d];
    const float b0  = bias[0];
    __syncthreads();

    const float* __restrict__ xb = x + (size_t)b * (Nc * Dc);

    float m   = -3.402823466e38f;   // running max
    float l   = 0.0f;               // running denom
    float acc = 0.0f;               // running weighted sum for this d

    // prefetch group 0
    float v[GROUP];
    #pragma unroll
    for (int j = 0; j < GROUP; j++)
        v[j] = xb[(size_t)s_idx[j] * Dc + d];

    #pragma unroll 1
    for (int g = 0; g < Kc / GROUP; g++) {
        // issue next group's loads early (hidden behind reduce + barriers)
        float nv[GROUP];
        const bool more = (g + 1 < Kc / GROUP);
        if (more) {
            #pragma unroll
            for (int j = 0; j < GROUP; j++)
                nv[j] = xb[(size_t)s_idx[(g + 1) * GROUP + j] * Dc + d];
        }

        // partial dot products for the current group
        float p[GROUP];
        #pragma unroll
        for (int j = 0; j < GROUP; j++) p[j] = w_d * v[j];

        // stage 1: intra-warp tree reduce (all 8 k's interleaved for ILP)
        #pragma unroll
        for (int off = 16; off > 0; off >>= 1) {
            #pragma unroll
            for (int j = 0; j < GROUP; j++)
                p[j] += __shfl_xor_sync(0xffffffffu, p[j], off);
        }
        if (lane == 0) {
            #pragma unroll
            for (int j = 0; j < GROUP; j++) s_part[j][warp] = p[j];
        }
        __syncthreads();

        // stage 2: warps 0..7 each reduce the 16 warp-partials of one k
        if (warp < GROUP) {
            float t = (lane < 16) ? s_part[warp][lane] : 0.0f;
            #pragma unroll
            for (int off = 8; off > 0; off >>= 1)
                t += __shfl_xor_sync(0xffffffffu, t, off);
            if (lane == 0) s_score[warp] = t + b0;
        }
        __syncthreads();

        // online softmax update, all in registers
        #pragma unroll
        for (int j = 0; j < GROUP; j++) {
            float s  = s_score[j];
            float mn = fmaxf(m, s);
            float c  = __expf(m - mn);
            float e  = __expf(s - mn);
            l   = fmaf(l,   c, e);
            acc = fmaf(acc, c, e * v[j]);
            m   = mn;
        }

        if (more) {
            #pragma unroll
            for (int j = 0; j < GROUP; j++) v[j] = nv[j];
        }
    }

    out[(size_t)blockIdx.x * Dc + d] = acc / l;
}

extern "C" void kernel_launch(void* const* d_in, const int* in_sizes, int n_in,
                              void* d_out, int out_size)
{
    const float* x    = (const float*)d_in[0];   // (B, N, D) f32
    const int*   ridx = (const int*)  d_in[1];   // (R, K) i32
    const float* W    = (const float*)d_in[2];   // (1, D) f32
    const float* bias = (const float*)d_in[3];   // (1,) f32
    float*       out  = (float*)d_out;           // (B, R, D) f32

    regional_attn_pool<<<Bc * Rc, Dc>>>(x, ridx, W, bias, out);
}

// round 4
// speedup vs baseline: 2.4113x; 2.4071x over previous
#include <cuda_runtime.h>
#include <math.h>

// RegionalAttentionPool: B=16, N=4096, D=512, R=64, K=128
// Two-pass: (1) dense scores y[b,n] = x[b,n,:].W + bias  (rows are shared
// across all (r,k) that reference them); (2) per-(b,r) softmax over 128
// gathered scores + weighted float4 accumulation with no reductions in the
// hot loop.

constexpr int Bc = 16;
constexpr int Nc = 4096;
constexpr int Dc = 512;
constexpr int Rc = 64;
constexpr int Kc = 128;
constexpr int D4 = Dc / 4;       // 128 float4 per row

__device__ float g_scores[Bc * Nc];   // 256 KB scratch

// ---------------------------------------------------------------------------
// Pass 1: one warp per row. 512 threads = 16 rows/CTA. Reads x once (dense).
// ---------------------------------------------------------------------------
__global__ __launch_bounds__(512, 2)
void score_pass(const float4* __restrict__ x4,
                const float4* __restrict__ W4,
                const float*  __restrict__ bias,
                float*        __restrict__ y)
{
    const int lane = threadIdx.x & 31;
    const int warp = threadIdx.x >> 5;                 // 0..15
    const int row  = blockIdx.x * 16 + warp;           // 0 .. B*N-1

    const float4* __restrict__ xr = x4 + (size_t)row * D4;

    float dot = 0.0f;
    #pragma unroll
    for (int j = 0; j < 4; j++) {
        float4 v = xr[j * 32 + lane];
        float4 w = W4[j * 32 + lane];
        dot = fmaf(v.x, w.x, dot);
        dot = fmaf(v.y, w.y, dot);
        dot = fmaf(v.z, w.z, dot);
        dot = fmaf(v.w, w.w, dot);
    }
    #pragma unroll
    for (int off = 16; off > 0; off >>= 1)
        dot += __shfl_xor_sync(0xffffffffu, dot, off);

    if (lane == 0) y[row] = dot + bias[0];
}

// ---------------------------------------------------------------------------
// Pass 2: one CTA per (b,r), 128 threads. Thread = one float4 of d.
// Softmax weights computed once in the prologue; hot loop is pure LDG+FMA.
// ---------------------------------------------------------------------------
__global__ __launch_bounds__(128)
void pool_pass(const float4* __restrict__ x4,
               const int*    __restrict__ ridx,
               const float*  __restrict__ y,
               float4*       __restrict__ out4)
{
    __shared__ float s_w[Kc];
    __shared__ int   s_idx[Kc];
    __shared__ float s_red[4];

    const int tid  = threadIdx.x;      // 0..127
    const int lane = tid & 31;
    const int warp = tid >> 5;         // 0..3
    const int r    = blockIdx.x % Rc;
    const int b    = blockIdx.x / Rc;

    // --- softmax over the 128 gathered scores (thread = one k) ---
    const int idx = ridx[r * Kc + tid];
    s_idx[tid] = idx;
    float s = y[b * Nc + idx];

    // block max
    float m = s;
    #pragma unroll
    for (int off = 16; off > 0; off >>= 1)
        m = fmaxf(m, __shfl_xor_sync(0xffffffffu, m, off));
    if (lane == 0) s_red[warp] = m;
    __syncthreads();
    m = fmaxf(fmaxf(s_red[0], s_red[1]), fmaxf(s_red[2], s_red[3]));

    float e = __expf(s - m);

    // block sum
    float l = e;
    #pragma unroll
    for (int off = 16; off > 0; off >>= 1)
        l += __shfl_xor_sync(0xffffffffu, l, off);
    __syncthreads();                 // s_red reuse hazard
    if (lane == 0) s_red[warp] = l;
    __syncthreads();
    l = (s_red[0] + s_red[1]) + (s_red[2] + s_red[3]);

    s_w[tid] = e / l;
    __syncthreads();

    // --- weighted sum: 128 rows, float4 per thread, MLP=8 ---
    const float4* __restrict__ xb = x4 + (size_t)b * (Nc * D4);

    float accx = 0.f, accy = 0.f, accz = 0.f, accw = 0.f;

    #pragma unroll 1
    for (int g = 0; g < Kc; g += 8) {
        float4 v[8];
        #pragma unroll
        for (int j = 0; j < 8; j++)
            v[j] = xb[(size_t)s_idx[g + j] * D4 + tid];
        #pragma unroll
        for (int j = 0; j < 8; j++) {
            const float wk = s_w[g + j];
            accx = fmaf(wk, v[j].x, accx);
            accy = fmaf(wk, v[j].y, accy);
            accz = fmaf(wk, v[j].z, accz);
            accw = fmaf(wk, v[j].w, accw);
        }
    }

    out4[(size_t)blockIdx.x * D4 + tid] = make_float4(accx, accy, accz, accw);
}

extern "C" void kernel_launch(void* const* d_in, const int* in_sizes, int n_in,
                              void* d_out, int out_size)
{
    const float4* x4   = (const float4*)d_in[0];   // (B, N, D) f32
    const int*    ridx = (const int*)   d_in[1];   // (R, K) i32
    const float4* W4   = (const float4*)d_in[2];   // (1, D) f32
    const float*  bias = (const float*) d_in[3];   // (1,) f32
    float4*       out4 = (float4*)d_out;           // (B, R, D) f32

    float* y = nullptr;
    cudaGetSymbolAddress((void**)&y, g_scores);

    score_pass<<<(Bc * Nc) / 16, 512>>>(x4, W4, bias, y);
    pool_pass<<<Bc * Rc, 128>>>(x4, ridx, y, (float4*)d_out);
    (void)in_sizes; (void)n_in; (void)out_size; (void)out4;
}